// round 5
// baseline (speedup 1.0000x reference)
#include <cuda_runtime.h>
#include <cstdint>

#define NN    8192
#define FIN   128
#define FOUT  64
#define ALPHA 0.2f
#define LOG2E 1.4426950408889634f

#define TI    128
#define SPLIT 4
#define JH    (NN/SPLIT)   // 2048
#define KC    32
#define NCH   (JH/KC)      // 64
#define NSTAGE 3

#define A_STRIDE 40
#define B_STRIDE 68
#define A_BUF  (TI*A_STRIDE*4)      // 20480
#define B_BUF  (KC*B_STRIDE*4)      // 8704
#define EF_BUF (KC*8)               // 256
#define STAGE_BYTES (A_BUF + B_BUF + EF_BUF)   // 29440
#define GAT_SMEM (NSTAGE*STAGE_BYTES + 256)

// ---------------- device scratch ----------------
__device__ float  g_h[(size_t)NN * FOUT];    // h [node][f], tf32-rounded
__device__ float2 g_EF1[NN];                 // {exp2(s1'), exp2(0.2 s1')}
__device__ float2 g_EF2[NN];
__device__ float  g_part[SPLIT][(size_t)NN * FOUT];
__device__ float  g_wsum[SPLIT][NN];
__device__ int    g_cnt[NN / TI];

// ---------------- helpers ----------------
__device__ __forceinline__ float ex2f(float x) {
    float r; asm("ex2.approx.ftz.f32 %0, %1;" : "=f"(r) : "f"(x)); return r;
}
__device__ __forceinline__ uint32_t smem_u32(const void* p) {
    uint32_t a;
    asm("{ .reg .u64 t; cvta.to.shared.u64 t, %1; cvt.u32.u64 %0, t; }" : "=r"(a) : "l"(p));
    return a;
}
__device__ __forceinline__ float tf32r(float x) {
    uint32_t u; asm("cvt.rna.tf32.f32 %0, %1;" : "=r"(u) : "f"(x));
    return __uint_as_float(u);
}

#define CP16(dst, src) \
    asm volatile("cp.async.cg.shared.global [%0], [%1], 16;" :: "r"(dst), "l"(src) : "memory")
#define CP_COMMIT() asm volatile("cp.async.commit_group;" ::: "memory")
#define CP_WAIT2()  asm volatile("cp.async.wait_group 2;" ::: "memory")
#define CP_WAIT1()  asm volatile("cp.async.wait_group 1;" ::: "memory")
#define CP_WAIT0()  asm volatile("cp.async.wait_group 0;" ::: "memory")

__device__ __forceinline__ uint32_t lds_u32(uint32_t a) {
    uint32_t v; asm volatile("ld.shared.b32 %0, [%1];" : "=r"(v) : "r"(a)); return v;
}
__device__ __forceinline__ int2 lds_s64(uint32_t a) {
    int2 v; asm volatile("ld.shared.v2.u32 {%0,%1}, [%2];" : "=r"(v.x), "=r"(v.y) : "r"(a)); return v;
}
__device__ __forceinline__ float4 lds_f4(uint32_t a) {
    float4 v;
    asm volatile("ld.shared.v4.f32 {%0,%1,%2,%3}, [%4];"
                 : "=f"(v.x), "=f"(v.y), "=f"(v.z), "=f"(v.w) : "r"(a));
    return v;
}

#define MMA_TF32(c, a0, a1, a2, a3, b0, b1) \
    asm volatile("mma.sync.aligned.m16n8k8.row.col.f32.tf32.tf32.f32 " \
        "{%0,%1,%2,%3}, {%4,%5,%6,%7}, {%8,%9}, {%0,%1,%2,%3};" \
        : "+f"((c)[0]), "+f"((c)[1]), "+f"((c)[2]), "+f"((c)[3]) \
        : "r"(a0), "r"(a1), "r"(a2), "r"(a3), "r"(b0), "r"(b1))

// ===================== K1: projection + node tables + counter reset =====================
// 512 CTAs x 16 rows, 256 thr: thread = (rg 0..15 rows) x (cg 0..15 col-quads)
__global__ __launch_bounds__(256) void k_proj(const float* __restrict__ X,
                                              const float* __restrict__ W,
                                              const float* __restrict__ a1,
                                              const float* __restrict__ a2) {
    __shared__ float Ws[FIN * FOUT];          // 32 KB  [k][f]
    __shared__ float Xs[FIN * 17];            // 8.7 KB [k][row], stride 17

    const int tid = threadIdx.x;
    const int i0 = blockIdx.x * 16;

    if (blockIdx.x == 0 && tid < NN / TI) g_cnt[tid] = 0;

    {   // W fill
        const float4* W4 = (const float4*)W;
        float4* Ws4 = (float4*)Ws;
#pragma unroll
        for (int k = 0; k < 8; k++) Ws4[tid + k * 256] = W4[tid + k * 256];
    }
    {   // X transpose fill
        const int row = tid & 15;
        const int q0 = tid >> 4;
#pragma unroll
        for (int m = 0; m < 2; m++) {
            const int q = q0 + 16 * m;
            const float4 v = *(const float4*)(X + (size_t)(i0 + row) * FIN + 4 * q);
            Xs[(4 * q + 0) * 17 + row] = v.x;
            Xs[(4 * q + 1) * 17 + row] = v.y;
            Xs[(4 * q + 2) * 17 + row] = v.z;
            Xs[(4 * q + 3) * 17 + row] = v.w;
        }
    }
    __syncthreads();

    const int rg = tid >> 4;
    const int cg = tid & 15;
    const float4* Ws4 = (const float4*)Ws;

    float aA[4] = {0.f, 0.f, 0.f, 0.f}, aB[4] = {0.f, 0.f, 0.f, 0.f};
#pragma unroll 8
    for (int k = 0; k < FIN; k += 2) {
        const float x0 = Xs[k * 17 + rg];
        const float x1 = Xs[(k + 1) * 17 + rg];
        const float4 w0 = Ws4[k * 16 + cg];
        const float4 w1 = Ws4[(k + 1) * 16 + cg];
        aA[0] += x0 * w0.x; aA[1] += x0 * w0.y; aA[2] += x0 * w0.z; aA[3] += x0 * w0.w;
        aB[0] += x1 * w1.x; aB[1] += x1 * w1.y; aB[2] += x1 * w1.z; aB[3] += x1 * w1.w;
    }
    float acc[4];
#pragma unroll
    for (int c = 0; c < 4; c++) acc[c] = aA[c] + aB[c];

    // h (tf32-rounded), row-major [node][f]
    *(float4*)(g_h + (size_t)(i0 + rg) * FOUT + 4 * cg) =
        make_float4(tf32r(acc[0]), tf32r(acc[1]), tf32r(acc[2]), tf32r(acc[3]));

    const float4 a1v = ((const float4*)a1)[cg];
    const float4 a2v = ((const float4*)a2)[cg];
    float v1 = acc[0] * a1v.x + acc[1] * a1v.y + acc[2] * a1v.z + acc[3] * a1v.w;
    float v2 = acc[0] * a2v.x + acc[1] * a2v.y + acc[2] * a2v.z + acc[3] * a2v.w;
#pragma unroll
    for (int s = 8; s > 0; s >>= 1) {
        v1 += __shfl_xor_sync(0xffffffffu, v1, s, 16);
        v2 += __shfl_xor_sync(0xffffffffu, v2, s, 16);
    }
    if (cg == 0) {
        const float s1L = v1 * LOG2E;
        const float s2L = v2 * LOG2E;
        const int node = i0 + rg;
        g_EF1[node] = make_float2(ex2f(s1L), ex2f(ALPHA * s1L));
        g_EF2[node] = make_float2(ex2f(s2L), ex2f(ALPHA * s2L));
    }
}

// ===================== K2: fused masked softmax + aggregation + combine =====================
__global__ __launch_bounds__(256, 2) void k_gat(const int* __restrict__ A,
                                                float* __restrict__ out) {
    extern __shared__ char sm[];
    const uint32_t sb0 = smem_u32(sm);
    const uint32_t sb = (sb0 + 127u) & ~127u;

    const int tid  = threadIdx.x;
    const int wid  = tid >> 5;
    const int lane = tid & 31;
    const int qr   = lane >> 2;
    const int qc   = lane & 3;
    const int mg   = wid >> 1;
    const int ng   = wid & 1;
    const int ib   = blockIdx.x >> 2;
    const int sk   = blockIdx.x & 3;
    const int i0   = ib * TI;
    const int j0   = sk * JH;

    // fill mappings
    const int frow = tid >> 3;           // 0..31
    const int fseg = tid & 7;            // 0..7 (16B units)
    const int* aSrcBase = A + (size_t)i0 * NN + j0;
    const float* hSrcBase = g_h + (size_t)j0 * FOUT;

    float2 ef1[4];
#pragma unroll
    for (int k = 0; k < 4; k++) ef1[k] = g_EF1[i0 + mg * 32 + qr + 8 * k];

    float acc[2][4][4];
#pragma unroll
    for (int mt = 0; mt < 2; mt++)
#pragma unroll
        for (int nt = 0; nt < 4; nt++)
#pragma unroll
            for (int k = 0; k < 4; k++) acc[mt][nt][k] = 0.f;
    float wsum[4] = {0.f, 0.f, 0.f, 0.f};

#define ISSUE(T) do {                                                              \
        const int _s = (T) % NSTAGE;                                               \
        const uint32_t _base = sb + (uint32_t)(_s * STAGE_BYTES);                  \
        const int _jo = (T) * KC;                                                  \
        _Pragma("unroll")                                                          \
        for (int k = 0; k < 4; k++) {                                              \
            const int r = frow + 32 * k;                                           \
            CP16(_base + (uint32_t)(r * A_STRIDE + fseg * 4) * 4,                  \
                 aSrcBase + (size_t)r * NN + _jo + fseg * 4);                      \
        }                                                                          \
        _Pragma("unroll")                                                          \
        for (int m = 0; m < 2; m++) {                                              \
            const int sg = fseg + 8 * m;                                           \
            CP16(_base + A_BUF + (uint32_t)(frow * B_STRIDE + sg * 4) * 4,         \
                 hSrcBase + (size_t)(_jo + frow) * FOUT + sg * 4);                 \
        }                                                                          \
        if (tid < 16)                                                              \
            CP16(_base + A_BUF + B_BUF + (uint32_t)tid * 16,                       \
                 (const float2*)g_EF2 + j0 + _jo + tid * 2);                       \
        CP_COMMIT();                                                               \
    } while (0)

    ISSUE(0);
    ISSUE(1);

    for (int t = 0; t < NCH; t++) {
        if (t + 2 < NCH) { ISSUE(t + 2); CP_WAIT2(); }
        else if (t + 1 < NCH) { CP_WAIT1(); }
        else { CP_WAIT0(); }
        __syncthreads();

        const uint32_t aB = sb + (uint32_t)((t % NSTAGE) * STAGE_BYTES);
        const uint32_t bB = aB + A_BUF;
        const uint32_t eB = aB + A_BUF + B_BUF;

#pragma unroll
        for (int ks = 0; ks < 4; ks++) {
            const int j2 = 8 * ks + 2 * qc;                 // j for slot c=0 (c=1 -> j2+1)
            const float4 ef = lds_f4(eB + (uint32_t)j2 * 8);  // {E(j),F(j),E(j+1),F(j+1)}

            uint32_t b0[4], b1[4];
            const uint32_t bbase = bB + (uint32_t)(j2 * B_STRIDE + ng * 32 + qr) * 4;
#pragma unroll
            for (int nt = 0; nt < 4; nt++) {
                b0[nt] = lds_u32(bbase + (uint32_t)nt * 32);
                b1[nt] = lds_u32(bbase + (uint32_t)(B_STRIDE * 4) + (uint32_t)nt * 32);
            }

#pragma unroll
            for (int mt = 0; mt < 2; mt++) {
                const uint32_t abase =
                    aB + (uint32_t)((mg * 32 + mt * 16 + qr) * A_STRIDE + j2) * 4;
                const int2 alo = lds_s64(abase);
                const int2 ahi = lds_s64(abase + (uint32_t)(8 * A_STRIDE * 4));

                const float2 e1a = ef1[2 * mt];
                const float2 e1b = ef1[2 * mt + 1];
                float w00 = fmaxf(e1a.x * ef.x, e1a.y * ef.y); if (alo.x <= 0) w00 = 0.f;
                float w01 = fmaxf(e1a.x * ef.z, e1a.y * ef.w); if (alo.y <= 0) w01 = 0.f;
                float w10 = fmaxf(e1b.x * ef.x, e1b.y * ef.y); if (ahi.x <= 0) w10 = 0.f;
                float w11 = fmaxf(e1b.x * ef.z, e1b.y * ef.w); if (ahi.y <= 0) w11 = 0.f;
                wsum[2 * mt]     += w00 + w01;
                wsum[2 * mt + 1] += w10 + w11;

                const uint32_t ua0 = __float_as_uint(w00);
                const uint32_t ua1 = __float_as_uint(w10);
                const uint32_t ua2 = __float_as_uint(w01);
                const uint32_t ua3 = __float_as_uint(w11);
#pragma unroll
                for (int nt = 0; nt < 4; nt++)
                    MMA_TF32(acc[mt][nt], ua0, ua1, ua2, ua3, b0[nt], b1[nt]);
            }
        }
        __syncthreads();
    }

    // ---- epilogue: store partials ----
#pragma unroll
    for (int k = 0; k < 4; k++) {
        wsum[k] += __shfl_xor_sync(0xffffffffu, wsum[k], 1);
        wsum[k] += __shfl_xor_sync(0xffffffffu, wsum[k], 2);
    }
    if (ng == 0 && qc == 0) {
#pragma unroll
        for (int k = 0; k < 4; k++)
            g_wsum[sk][i0 + mg * 32 + qr + 8 * k] = wsum[k];
    }
#pragma unroll
    for (int mt = 0; mt < 2; mt++) {
        float* pr0 = &g_part[sk][(size_t)(i0 + mg * 32 + mt * 16 + qr) * FOUT];
        float* pr1 = &g_part[sk][(size_t)(i0 + mg * 32 + mt * 16 + qr + 8) * FOUT];
#pragma unroll
        for (int nt = 0; nt < 4; nt++) {
            const int c0 = ng * 32 + nt * 8 + 2 * qc;
            *(float2*)(pr0 + c0) = make_float2(acc[mt][nt][0], acc[mt][nt][1]);
            *(float2*)(pr1 + c0) = make_float2(acc[mt][nt][2], acc[mt][nt][3]);
        }
    }

    // ---- last split-K CTA for this i-block combines and divides ----
    __threadfence();
    __shared__ int isLast;
    if (tid == 0) isLast = (atomicAdd(&g_cnt[ib], 1) == SPLIT - 1) ? 1 : 0;
    __syncthreads();
    if (isLast) {
        __threadfence();
#pragma unroll
        for (int k = 0; k < 8; k++) {
            const int idx4 = tid + k * 256;              // float4 index within block
            const int row = idx4 >> 4;                   // local row
            const size_t e = (size_t)(i0 + row) * FOUT + (idx4 & 15) * 4;
            const float4 p0 = *(const float4*)&g_part[0][e];
            const float4 p1 = *(const float4*)&g_part[1][e];
            const float4 p2 = *(const float4*)&g_part[2][e];
            const float4 p3 = *(const float4*)&g_part[3][e];
            const float den = (g_wsum[0][i0 + row] + g_wsum[1][i0 + row]) +
                              (g_wsum[2][i0 + row] + g_wsum[3][i0 + row]);
            const float inv = 1.0f / den;
            float4 o;
            o.x = ((p0.x + p1.x) + (p2.x + p3.x)) * inv;
            o.y = ((p0.y + p1.y) + (p2.y + p3.y)) * inv;
            o.z = ((p0.z + p1.z) + (p2.z + p3.z)) * inv;
            o.w = ((p0.w + p1.w) + (p2.w + p3.w)) * inv;
            *(float4*)(out + e) = o;
        }
    }
}

extern "C" void kernel_launch(void* const* d_in, const int* in_sizes, int n_in,
                              void* d_out, int out_size) {
    const float* X  = (const float*)d_in[0];
    const int*   A  = (const int*)d_in[1];
    const float* W  = (const float*)d_in[2];
    const float* a1 = (const float*)d_in[3];
    const float* a2 = (const float*)d_in[4];
    float* out = (float*)d_out;

    cudaFuncSetAttribute(k_gat, cudaFuncAttributeMaxDynamicSharedMemorySize, GAT_SMEM);

    k_proj<<<NN / 16, 256>>>(X, W, a1, a2);
    k_gat<<<(NN / TI) * SPLIT, 256, GAT_SMEM>>>(A, out);
}